// round 4
// baseline (speedup 1.0000x reference)
#include <cuda_runtime.h>

#define Bn 2048
#define NB 2000
#define DB 30
#define KK 20
#define LL 40
#define PP 2

typedef unsigned long long u64;

// Scratch (no allocations allowed in kernel_launch)
__device__ float d_wact[NB * LL];          // sigmoid((r - kappa))        [NB, L]
__device__ float d_gT[LL * Bn];            // g transposed                [L, B]
__device__ float d_partial[LL * KK * Bn];  // alpha-weighted per-(l,k)    [L, K, B]

// ---------------- packed f32x2 helpers --------------------------------------
__device__ __forceinline__ u64 pack2(float lo, float hi) {
    u64 r; asm("mov.b64 %0, {%1, %2};" : "=l"(r) : "f"(lo), "f"(hi)); return r;
}
__device__ __forceinline__ void unpack2(u64 v, float& lo, float& hi) {
    asm("mov.b64 {%0, %1}, %2;" : "=f"(lo), "=f"(hi) : "l"(v));
}
__device__ __forceinline__ u64 ffma2(u64 a, u64 b, u64 c) {
    u64 d; asm("fma.rn.f32x2 %0, %1, %2, %3;" : "=l"(d) : "l"(a), "l"(b), "l"(c)); return d;
}
__device__ __forceinline__ u64 fadd2(u64 a, u64 b) {
    u64 d; asm("add.rn.f32x2 %0, %1, %2;" : "=l"(d) : "l"(a), "l"(b)); return d;
}
__device__ __forceinline__ u64 fmul2(u64 a, u64 b) {
    u64 d; asm("mul.rn.f32x2 %0, %1, %2;" : "=l"(d) : "l"(a), "l"(b)); return d;
}
__device__ __forceinline__ float ex2(float x) {
    float r; asm("ex2.approx.f32 %0, %1;" : "=f"(r) : "f"(x)); return r;
}
// elu(z)+1 = max(z,0) + exp2(min(z,0)*log2e); the -1 is absorbed into the
// next layer's bias (b' = b - rowsum(W)).
__device__ __forceinline__ float elup1(float z) {
    return fmaxf(z, 0.f) + ex2(fminf(z, 0.f) * 1.44269504f);
}
__device__ __forceinline__ u64 elup1_2(u64 z) {
    float lo, hi; unpack2(z, lo, hi);
    return pack2(elup1(lo), elup1(hi));
}

// ---------------------------------------------------------------------------
// Kernel A: w_act[m,l] = sigmoid(r[l] - ||ml[m]-mu[l]||^2), smem-staged.
// Block: 32 m-rows; 256 threads = 32 m x 8 l-groups (5 l each).
// ---------------------------------------------------------------------------
#define MT 32
#define DPAD 32

__global__ __launch_bounds__(256) void k_wact(const float* __restrict__ ml,
                                              const float* __restrict__ mu,
                                              const float* __restrict__ r) {
    __shared__ __align__(16) float s_mu[LL * DPAD];
    __shared__ __align__(16) float s_ml[MT * DPAD];
    __shared__ float s_r[LL];
    int tid = threadIdx.x;
    int m0  = blockIdx.x * MT;

    for (int e = tid; e < LL * DB; e += 256) {
        int l = e / DB, d = e % DB;
        s_mu[l * DPAD + d] = mu[e];
    }
    for (int e = tid; e < MT * DB; e += 256) {
        int mm = e / DB, d = e % DB;
        int m = m0 + mm;
        s_ml[mm * DPAD + d] = (m < NB) ? ml[m * DB + d] : 0.f;
    }
    if (tid < LL) s_r[tid] = r[tid];
    __syncthreads();

    int mm = tid & 31;          // local m
    int lg = tid >> 5;          // 0..7, 5 l's each
    int m  = m0 + mm;
    if (m >= NB) return;

    float a[DB];
#pragma unroll
    for (int d = 0; d < DB; d++) a[d] = s_ml[mm * DPAD + d];

#pragma unroll
    for (int li = 0; li < 5; li++) {
        int l = lg * 5 + li;
        const float* c = &s_mu[l * DPAD];
        float s = 0.f;
#pragma unroll
        for (int d = 0; d < DB; d++) { float t = a[d] - c[d]; s = fmaf(t, t, s); }
        float z = s_r[l] - s;
        d_wact[m * LL + l] = 1.0f / (1.0f + __expf(-z));
    }
}

// ---------------------------------------------------------------------------
// Kernel B: gT[l,b] = sum_m x[b,m] * w_act[m,l]
// 16 b-rows x 40 l-cols per block; ws transposed [l][mm], mm unrolled by 4,
// packed ffma2 along K.
// ---------------------------------------------------------------------------
#define CH 128
#define XS 136          // float stride: conflict-free rows, 16B aligned
#define WS 136

__global__ __launch_bounds__(320) void k_gemm(const float* __restrict__ x) {
    __shared__ __align__(16) float xs[16 * XS];
    __shared__ __align__(16) float ws[LL * WS];     // [l][mm]
    int b0  = blockIdx.x * 16;
    int tid = threadIdx.x;
    int row = tid & 15;
    int cg  = tid >> 4;            // 0..19, cols 2cg, 2cg+1
    u64 acc0 = 0ull, acc1 = 0ull;
    for (int m0 = 0; m0 < NB; m0 += CH) {
        for (int e = tid; e < 16 * CH; e += 320) {
            int rr = e >> 7, cc = e & (CH - 1);
            int m = m0 + cc;
            xs[rr * XS + cc] = (m < NB) ? x[(b0 + rr) * NB + m] : 0.f;
        }
        for (int e = tid; e < CH * LL; e += 320) {
            int mm = e / LL, l = e % LL;
            int m = m0 + mm;
            ws[l * WS + mm] = (m < NB) ? d_wact[m * LL + l] : 0.f;
        }
        __syncthreads();
#pragma unroll 4
        for (int mm = 0; mm < CH; mm += 4) {
            float4 xv = *(const float4*)&xs[row * XS + mm];
            float4 w0 = *(const float4*)&ws[(2 * cg)     * WS + mm];
            float4 w1 = *(const float4*)&ws[(2 * cg + 1) * WS + mm];
            u64 xa = pack2(xv.x, xv.y), xb = pack2(xv.z, xv.w);
            acc0 = ffma2(xa, pack2(w0.x, w0.y), acc0);
            acc0 = ffma2(xb, pack2(w0.z, w0.w), acc0);
            acc1 = ffma2(xa, pack2(w1.x, w1.y), acc1);
            acc1 = ffma2(xb, pack2(w1.z, w1.w), acc1);
        }
        __syncthreads();
    }
    float a0l, a0h, a1l, a1h;
    unpack2(acc0, a0l, a0h);
    unpack2(acc1, a1l, a1h);
    d_gT[(2 * cg)     * Bn + b0 + row] = a0l + a0h;
    d_gT[(2 * cg + 1) * Bn + b0 + row] = a1l + a1h;
}

// ---------------------------------------------------------------------------
// Kernel C: NAM, packed f32x2, TWO pairs per thread per pass (each weight LDS
// feeds 4 ffma2 chains). Biases of layers 2..4 pre-adjusted by -rowsum(W) so
// ELU is elu+1 (no -1). grid is split in half by the launcher (h = 0/1).
// ---------------------------------------------------------------------------
__global__ __launch_bounds__(256) void k_nam(
    const float* __restrict__ W1, const float* __restrict__ b1,
    const float* __restrict__ W2, const float* __restrict__ b2,
    const float* __restrict__ W3, const float* __restrict__ b3,
    const float* __restrict__ W4, const float* __restrict__ b4,
    const float* __restrict__ alpha, int blk0) {
    __shared__ __align__(16) u64 sW1d[PP][16], sB1d[PP][16], sB2d[PP][16];
    __shared__ __align__(16) u64 sW2d[PP][16][16];   // [p][j][i] = dup(W2[klp,i,j])
    __shared__ __align__(16) u64 sW3d[PP][8][16];    // [p][j][i] = dup(W3[klp,i,j])
    __shared__ __align__(16) u64 sB3d[PP][8], sW4d[PP][8];
    __shared__ __align__(16) u64 sB4d[PP];

    int bid = blockIdx.x + blk0;
    int k = bid / LL, l = bid % LL;
    int tid  = threadIdx.x;
    int base = (k * LL + l) * PP;       // flat klp index of p=0

    if (tid < 32) {
        int p = tid >> 4, i = tid & 15;
        float w = W1[base * 16 + tid];  sW1d[p][i] = pack2(w, w);
        float a = b1[base * 16 + tid];  sB1d[p][i] = pack2(a, a);
        float c = b2[base * 16 + tid];
        const float* w2p = W2 + base * 256 + p * 256;   // [i][j]
#pragma unroll
        for (int ii = 0; ii < 16; ii++) c -= w2p[ii * 16 + i];
        sB2d[p][i] = pack2(c, c);
    }
#pragma unroll
    for (int e = tid; e < PP * 256; e += 256) {      // W2[p][i][j] -> sW2d[p][j][i]
        int p = e >> 8, i = (e >> 4) & 15, j = e & 15;
        float w = W2[base * 256 + e];
        sW2d[p][j][i] = pack2(w, w);
    }
    if (tid < PP * 128) {                            // W3[p][i(16)][j(8)] -> sW3d[p][j][i]
        int p = tid >> 7, i = (tid >> 3) & 15, j = tid & 7;
        float w = W3[base * 128 + tid];
        sW3d[p][j][i] = pack2(w, w);
    }
    if (tid < 16) {
        int p = tid >> 3, j = tid & 7;
        float a = b3[base * 8 + tid];
        const float* w3p = W3 + base * 128 + p * 128;
#pragma unroll
        for (int ii = 0; ii < 16; ii++) a -= w3p[ii * 8 + j];
        sB3d[p][j] = pack2(a, a);
        float w = W4[base * 8 + tid];  sW4d[p][j] = pack2(w, w);
    }
    if (tid < 2) {
        float a = b4[base + tid];
        const float* w4p = W4 + base * 8 + tid * 8;
#pragma unroll
        for (int ii = 0; ii < 8; ii++) a -= w4p[ii];
        sB4d[tid] = pack2(a, a);
    }
    __syncthreads();

    float aAct = 1.0f / (1.0f + __expf(-alpha[l * KK + k]));
    u64 aAct2 = pack2(aAct, aAct);
    float* outp = d_partial + (l * KK + k) * Bn;
    const float* gp = d_gT + l * Bn;

#pragma unroll 1
    for (int pass = 0; pass < 2; pass++) {
        int b0 = pass * 1024 + 2 * tid;             // pair0 at b0, pair1 at b0+512
        float2 g0 = *(const float2*)&gp[b0];
        float2 g1 = *(const float2*)&gp[b0 + 512];
        u64 G0 = pack2(g0.x, g0.y);
        u64 G1 = pack2(g1.x, g1.y);
        u64 S0 = 0ull, S1 = 0ull;

#pragma unroll 1
        for (int p = 0; p < PP; p++) {
            u64 t1[16][2];
#pragma unroll
            for (int i = 0; i < 16; i++) {
                u64 w = sW1d[p][i], bb = sB1d[p][i];
                t1[i][0] = elup1_2(ffma2(G0, w, bb));
                t1[i][1] = elup1_2(ffma2(G1, w, bb));
            }

            u64 t2[16][2];
#pragma unroll
            for (int j = 0; j < 16; j++) {
                const ulonglong2* wr = (const ulonglong2*)sW2d[p][j];
                u64 bias = sB2d[p][j];
                u64 e0 = bias, o0 = 0ull, e1 = bias, o1 = 0ull;
#pragma unroll
                for (int q = 0; q < 8; q++) {
                    ulonglong2 w = wr[q];
                    e0 = ffma2(t1[2 * q][0],     w.x, e0);
                    o0 = ffma2(t1[2 * q + 1][0], w.y, o0);
                    e1 = ffma2(t1[2 * q][1],     w.x, e1);
                    o1 = ffma2(t1[2 * q + 1][1], w.y, o1);
                }
                t2[j][0] = elup1_2(fadd2(e0, o0));
                t2[j][1] = elup1_2(fadd2(e1, o1));
            }

            u64 t3[8][2];
#pragma unroll
            for (int j = 0; j < 8; j++) {
                const ulonglong2* wr = (const ulonglong2*)sW3d[p][j];
                u64 bias = sB3d[p][j];
                u64 e0 = bias, o0 = 0ull, e1 = bias, o1 = 0ull;
#pragma unroll
                for (int q = 0; q < 8; q++) {
                    ulonglong2 w = wr[q];
                    e0 = ffma2(t2[2 * q][0],     w.x, e0);
                    o0 = ffma2(t2[2 * q + 1][0], w.y, o0);
                    e1 = ffma2(t2[2 * q][1],     w.x, e1);
                    o1 = ffma2(t2[2 * q + 1][1], w.y, o1);
                }
                t3[j][0] = elup1_2(fadd2(e0, o0));
                t3[j][1] = elup1_2(fadd2(e1, o1));
            }

            {
                const ulonglong2* wr = (const ulonglong2*)sW4d[p];
                u64 bias = sB4d[p];
                u64 e0 = bias, o0 = 0ull, e1 = bias, o1 = 0ull;
#pragma unroll
                for (int q = 0; q < 4; q++) {
                    ulonglong2 w = wr[q];
                    e0 = ffma2(t3[2 * q][0],     w.x, e0);
                    o0 = ffma2(t3[2 * q + 1][0], w.y, o0);
                    e1 = ffma2(t3[2 * q][1],     w.x, e1);
                    o1 = ffma2(t3[2 * q + 1][1], w.y, o1);
                }
                S0 = fadd2(S0, fadd2(e0, o0));
                S1 = fadd2(S1, fadd2(e1, o1));
            }
        }

        u64 r0 = fmul2(aAct2, S0);
        u64 r1 = fmul2(aAct2, S1);
        float lo, hi;
        unpack2(r0, lo, hi); *(float2*)&outp[b0]       = make_float2(lo, hi);
        unpack2(r1, lo, hi); *(float2*)&outp[b0 + 512] = make_float2(lo, hi);
    }
}

// ---------------------------------------------------------------------------
// Kernel D: out[b,k] = beta[k] + sum_l partial[l,k,b]
// ---------------------------------------------------------------------------
__global__ void k_out(const float* __restrict__ beta, float* __restrict__ out) {
    int idx = blockIdx.x * blockDim.x + threadIdx.x;
    if (idx >= KK * Bn) return;
    int k = idx >> 11;       // /2048
    int b = idx & (Bn - 1);
    float s = beta[k];
#pragma unroll
    for (int l = 0; l < LL; l++) s += d_partial[(l * KK + k) * Bn + b];
    out[b * KK + k] = s;
}

// ---------------------------------------------------------------------------
extern "C" void kernel_launch(void* const* d_in, const int* in_sizes, int n_in,
                              void* d_out, int out_size) {
    const float* x     = (const float*)d_in[0];
    const float* ml    = (const float*)d_in[1];
    const float* mu    = (const float*)d_in[2];
    const float* r     = (const float*)d_in[3];
    const float* alpha = (const float*)d_in[4];
    const float* beta  = (const float*)d_in[5];
    const float* W1    = (const float*)d_in[6];
    const float* b1    = (const float*)d_in[7];
    const float* W2    = (const float*)d_in[8];
    const float* b2    = (const float*)d_in[9];
    const float* W3    = (const float*)d_in[10];
    const float* b3    = (const float*)d_in[11];
    const float* W4    = (const float*)d_in[12];
    const float* b4    = (const float*)d_in[13];
    float* out = (float*)d_out;

    k_wact<<<(NB + MT - 1) / MT, 256>>>(ml, mu, r);
    k_gemm<<<Bn / 16, 320>>>(x);
    k_nam<<<KK * LL / 2, 256>>>(W1, b1, W2, b2, W3, b3, W4, b4, alpha, 0);
    k_nam<<<KK * LL / 2, 256>>>(W1, b1, W2, b2, W3, b3, W4, b4, alpha, KK * LL / 2);
    k_out<<<(KK * Bn + 255) / 256, 256>>>(beta, out);
}

// round 5
// speedup vs baseline: 1.0017x; 1.0017x over previous
#include <cuda_runtime.h>

#define Bn 2048
#define NB 2000
#define DB 30
#define KK 20
#define LL 40
#define PP 2

typedef unsigned long long u64;

#define LOG2E 1.44269504088896f
#define LN2   0.69314718055995f

// Scratch (no allocations allowed in kernel_launch)
__device__ float d_wact[NB * LL];          // sigmoid((r - kappa))        [NB, L]
__device__ float d_gT[LL * Bn];            // g transposed                [L, B]
__device__ float d_partial[LL * KK * Bn];  // alpha-weighted per-(l,k)    [L, K, B]

// ---------------- packed f32x2 helpers --------------------------------------
__device__ __forceinline__ u64 pack2(float lo, float hi) {
    u64 r; asm("mov.b64 %0, {%1, %2};" : "=l"(r) : "f"(lo), "f"(hi)); return r;
}
__device__ __forceinline__ void unpack2(u64 v, float& lo, float& hi) {
    asm("mov.b64 {%0, %1}, %2;" : "=f"(lo), "=f"(hi) : "l"(v));
}
__device__ __forceinline__ u64 ffma2(u64 a, u64 b, u64 c) {
    u64 d; asm("fma.rn.f32x2 %0, %1, %2, %3;" : "=l"(d) : "l"(a), "l"(b), "l"(c)); return d;
}
__device__ __forceinline__ u64 fadd2(u64 a, u64 b) {
    u64 d; asm("add.rn.f32x2 %0, %1, %2;" : "=l"(d) : "l"(a), "l"(b)); return d;
}
__device__ __forceinline__ u64 fmul2(u64 a, u64 b) {
    u64 d; asm("mul.rn.f32x2 %0, %1, %2;" : "=l"(d) : "l"(a), "l"(b)); return d;
}
__device__ __forceinline__ float ex2(float x) {
    float r; asm("ex2.approx.f32 %0, %1;" : "=f"(r) : "f"(x)); return r;
}
// Input z' is pre-scaled by log2e (weights/biases folded). True elu(z)+1 =
// ln2*max(z',0) + exp2(min(z',0)) -> FMNMX,FMNMX (alu) + MUFU + FFMA (fma).
__device__ __forceinline__ float elup1s(float zp) {
    return fmaf(fmaxf(zp, 0.f), LN2, ex2(fminf(zp, 0.f)));
}
__device__ __forceinline__ u64 elup1s_2(u64 z) {
    float lo, hi; unpack2(z, lo, hi);
    return pack2(elup1s(lo), elup1s(hi));
}

// ---------------------------------------------------------------------------
// Kernel A: w_act[m,l] = sigmoid(r[l] - ||ml[m]-mu[l]||^2), smem-staged.
// ---------------------------------------------------------------------------
#define MT 32
#define DPAD 32

__global__ __launch_bounds__(256) void k_wact(const float* __restrict__ ml,
                                              const float* __restrict__ mu,
                                              const float* __restrict__ r) {
    __shared__ __align__(16) float s_mu[LL * DPAD];
    __shared__ __align__(16) float s_ml[MT * DPAD];
    __shared__ float s_r[LL];
    int tid = threadIdx.x;
    int m0  = blockIdx.x * MT;

    for (int e = tid; e < LL * DB; e += 256) {
        int l = e / DB, d = e % DB;
        s_mu[l * DPAD + d] = mu[e];
    }
    for (int e = tid; e < MT * DB; e += 256) {
        int mm = e / DB, d = e % DB;
        int m = m0 + mm;
        s_ml[mm * DPAD + d] = (m < NB) ? ml[m * DB + d] : 0.f;
    }
    if (tid < LL) s_r[tid] = r[tid];
    __syncthreads();

    int mm = tid & 31;
    int lg = tid >> 5;
    int m  = m0 + mm;
    if (m >= NB) return;

    float a[DB];
#pragma unroll
    for (int d = 0; d < DB; d++) a[d] = s_ml[mm * DPAD + d];

#pragma unroll
    for (int li = 0; li < 5; li++) {
        int l = lg * 5 + li;
        const float* c = &s_mu[l * DPAD];
        float s = 0.f;
#pragma unroll
        for (int d = 0; d < DB; d++) { float t = a[d] - c[d]; s = fmaf(t, t, s); }
        float z = s_r[l] - s;
        d_wact[m * LL + l] = 1.0f / (1.0f + __expf(-z));
    }
}

// ---------------------------------------------------------------------------
// Kernel B: gT[l,b] = sum_m x[b,m] * w_act[m,l]
// ---------------------------------------------------------------------------
#define CH 128
#define XS 136
#define WS 136

__global__ __launch_bounds__(320) void k_gemm(const float* __restrict__ x) {
    __shared__ __align__(16) float xs[16 * XS];
    __shared__ __align__(16) float ws[LL * WS];     // [l][mm]
    int b0  = blockIdx.x * 16;
    int tid = threadIdx.x;
    int row = tid & 15;
    int cg  = tid >> 4;
    u64 acc0 = 0ull, acc1 = 0ull;
    for (int m0 = 0; m0 < NB; m0 += CH) {
        for (int e = tid; e < 16 * CH; e += 320) {
            int rr = e >> 7, cc = e & (CH - 1);
            int m = m0 + cc;
            xs[rr * XS + cc] = (m < NB) ? x[(b0 + rr) * NB + m] : 0.f;
        }
        for (int e = tid; e < CH * LL; e += 320) {
            int mm = e / LL, l = e % LL;
            int m = m0 + mm;
            ws[l * WS + mm] = (m < NB) ? d_wact[m * LL + l] : 0.f;
        }
        __syncthreads();
#pragma unroll 4
        for (int mm = 0; mm < CH; mm += 4) {
            float4 xv = *(const float4*)&xs[row * XS + mm];
            float4 w0 = *(const float4*)&ws[(2 * cg)     * WS + mm];
            float4 w1 = *(const float4*)&ws[(2 * cg + 1) * WS + mm];
            u64 xa = pack2(xv.x, xv.y), xb = pack2(xv.z, xv.w);
            acc0 = ffma2(xa, pack2(w0.x, w0.y), acc0);
            acc0 = ffma2(xb, pack2(w0.z, w0.w), acc0);
            acc1 = ffma2(xa, pack2(w1.x, w1.y), acc1);
            acc1 = ffma2(xb, pack2(w1.z, w1.w), acc1);
        }
        __syncthreads();
    }
    float a0l, a0h, a1l, a1h;
    unpack2(acc0, a0l, a0h);
    unpack2(acc1, a1l, a1h);
    d_gT[(2 * cg)     * Bn + b0 + row] = a0l + a0h;
    d_gT[(2 * cg + 1) * Bn + b0 + row] = a1l + a1h;
}

// ---------------------------------------------------------------------------
// Kernel C: NAM. 1 pair (2 batch elems) per thread, 4 passes; 2 blocks/SM.
// Layers 1-3 weights & (elu+1-adjusted) biases pre-scaled by log2e so ELU is
// max/min + ex2 + fma(ln2). Layer 4 unscaled.
// ---------------------------------------------------------------------------
__global__ __launch_bounds__(256, 2) void k_nam(
    const float* __restrict__ W1, const float* __restrict__ b1,
    const float* __restrict__ W2, const float* __restrict__ b2,
    const float* __restrict__ W3, const float* __restrict__ b3,
    const float* __restrict__ W4, const float* __restrict__ b4,
    const float* __restrict__ alpha, int blk0) {
    __shared__ __align__(16) ulonglong2 sL1[PP][16];   // (w_dup, b_dup), *log2e
    __shared__ __align__(16) u64 sB2d[PP][16];         // (b2 - rowsum W2)*log2e
    __shared__ __align__(16) u64 sW2d[PP][16][16];     // dup(W2[i][j])*log2e at [p][j][i]
    __shared__ __align__(16) u64 sW3d[PP][8][16];      // dup(W3[i][j])*log2e at [p][j][i]
    __shared__ __align__(16) u64 sB3d[PP][8], sW4d[PP][8];  // b3 adj *log2e; W4 raw
    __shared__ __align__(16) u64 sB4d[PP];             // b4 - rowsum W4 (raw)

    int bid = blockIdx.x + blk0;
    int k = bid / LL, l = bid % LL;
    int tid  = threadIdx.x;
    int base = (k * LL + l) * PP;

    if (tid < 32) {
        int p = tid >> 4, i = tid & 15;
        float w = W1[base * 16 + tid] * LOG2E;
        float a = b1[base * 16 + tid] * LOG2E;
        sL1[p][i] = make_ulonglong2(pack2(w, w), pack2(a, a));
        float c = b2[base * 16 + tid];
        const float* w2p = W2 + base * 256 + p * 256;
#pragma unroll
        for (int ii = 0; ii < 16; ii++) c -= w2p[ii * 16 + i];
        c *= LOG2E;
        sB2d[p][i] = pack2(c, c);
    }
#pragma unroll
    for (int e = tid; e < PP * 256; e += 256) {
        int p = e >> 8, i = (e >> 4) & 15, j = e & 15;
        float w = W2[base * 256 + e] * LOG2E;
        sW2d[p][j][i] = pack2(w, w);
    }
    if (tid < PP * 128) {
        int p = tid >> 7, i = (tid >> 3) & 15, j = tid & 7;
        float w = W3[base * 128 + tid] * LOG2E;
        sW3d[p][j][i] = pack2(w, w);
    }
    if (tid < 16) {
        int p = tid >> 3, j = tid & 7;
        float a = b3[base * 8 + tid];
        const float* w3p = W3 + base * 128 + p * 128;
#pragma unroll
        for (int ii = 0; ii < 16; ii++) a -= w3p[ii * 8 + j];
        a *= LOG2E;
        sB3d[p][j] = pack2(a, a);
        float w = W4[base * 8 + tid];  sW4d[p][j] = pack2(w, w);
    }
    if (tid < 2) {
        float a = b4[base + tid];
        const float* w4p = W4 + base * 8 + tid * 8;
#pragma unroll
        for (int ii = 0; ii < 8; ii++) a -= w4p[ii];
        sB4d[tid] = pack2(a, a);
    }
    __syncthreads();

    float aAct = 1.0f / (1.0f + __expf(-alpha[l * KK + k]));
    u64 aAct2 = pack2(aAct, aAct);
    float* outp = d_partial + (l * KK + k) * Bn;
    const float* gp = d_gT + l * Bn;

#pragma unroll 1
    for (int pass = 0; pass < 4; pass++) {
        int b0 = pass * 512 + 2 * tid;
        float2 g = *(const float2*)&gp[b0];
        u64 G = pack2(g.x, g.y);
        u64 S = 0ull;

#pragma unroll 1
        for (int p = 0; p < PP; p++) {
            u64 t1[16];
#pragma unroll
            for (int i = 0; i < 16; i++) {
                ulonglong2 wb = sL1[p][i];
                t1[i] = elup1s_2(ffma2(G, wb.x, wb.y));
            }

            u64 t2[16];
#pragma unroll
            for (int j = 0; j < 16; j++) {
                const ulonglong2* wr = (const ulonglong2*)sW2d[p][j];
                u64 e = sB2d[p][j], o = 0ull;
#pragma unroll
                for (int q = 0; q < 8; q++) {
                    ulonglong2 w = wr[q];
                    e = ffma2(t1[2 * q],     w.x, e);
                    o = ffma2(t1[2 * q + 1], w.y, o);
                }
                t2[j] = elup1s_2(fadd2(e, o));
            }

            u64 t3[8];
#pragma unroll
            for (int j = 0; j < 8; j++) {
                const ulonglong2* wr = (const ulonglong2*)sW3d[p][j];
                u64 e = sB3d[p][j], o = 0ull;
#pragma unroll
                for (int q = 0; q < 8; q++) {
                    ulonglong2 w = wr[q];
                    e = ffma2(t2[2 * q],     w.x, e);
                    o = ffma2(t2[2 * q + 1], w.y, o);
                }
                t3[j] = elup1s_2(fadd2(e, o));
            }

            {
                const ulonglong2* wr = (const ulonglong2*)sW4d[p];
                u64 e = sB4d[p], o = 0ull;
#pragma unroll
                for (int q = 0; q < 4; q++) {
                    ulonglong2 w = wr[q];
                    e = ffma2(t3[2 * q],     w.x, e);
                    o = ffma2(t3[2 * q + 1], w.y, o);
                }
                S = fadd2(S, fadd2(e, o));
            }
        }

        u64 res = fmul2(aAct2, S);
        float lo, hi;
        unpack2(res, lo, hi);
        *(float2*)&outp[b0] = make_float2(lo, hi);
    }
}

// ---------------------------------------------------------------------------
// Kernel D: out[b,k] = beta[k] + sum_l partial[l,k,b]
// ---------------------------------------------------------------------------
__global__ void k_out(const float* __restrict__ beta, float* __restrict__ out) {
    int idx = blockIdx.x * blockDim.x + threadIdx.x;
    if (idx >= KK * Bn) return;
    int k = idx >> 11;
    int b = idx & (Bn - 1);
    float s = beta[k];
#pragma unroll
    for (int l = 0; l < LL; l++) s += d_partial[(l * KK + k) * Bn + b];
    out[b * KK + k] = s;
}

// ---------------------------------------------------------------------------
extern "C" void kernel_launch(void* const* d_in, const int* in_sizes, int n_in,
                              void* d_out, int out_size) {
    const float* x     = (const float*)d_in[0];
    const float* ml    = (const float*)d_in[1];
    const float* mu    = (const float*)d_in[2];
    const float* r     = (const float*)d_in[3];
    const float* alpha = (const float*)d_in[4];
    const float* beta  = (const float*)d_in[5];
    const float* W1    = (const float*)d_in[6];
    const float* b1    = (const float*)d_in[7];
    const float* W2    = (const float*)d_in[8];
    const float* b2    = (const float*)d_in[9];
    const float* W3    = (const float*)d_in[10];
    const float* b3    = (const float*)d_in[11];
    const float* W4    = (const float*)d_in[12];
    const float* b4    = (const float*)d_in[13];
    float* out = (float*)d_out;

    k_wact<<<(NB + MT - 1) / MT, 256>>>(ml, mu, r);
    k_gemm<<<Bn / 16, 320>>>(x);
    k_nam<<<KK * LL / 2, 256>>>(W1, b1, W2, b2, W3, b3, W4, b4, alpha, 0);
    k_nam<<<KK * LL / 2, 256>>>(W1, b1, W2, b2, W3, b3, W4, b4, alpha, KK * LL / 2);
    k_out<<<(KK * Bn + 255) / 256, 256>>>(beta, out);
}

// round 6
// speedup vs baseline: 1.1838x; 1.1818x over previous
#include <cuda_runtime.h>

#define Bn 2048
#define NB 2000
#define DB 30
#define KK 20
#define LL 40
#define PP 2

typedef unsigned long long u64;

#define LOG2E 1.44269504088896f
#define LN2   0.69314718055995f

// Scratch (no allocations allowed in kernel_launch)
__device__ float d_wact[NB * LL];          // sigmoid((r - kappa))        [NB, L]
__device__ float d_gT[LL * Bn];            // g transposed                [L, B]
__device__ float d_partial[LL * KK * Bn];  // alpha-weighted per-(l,k)    [L, K, B]

// ---------------- packed f32x2 helpers --------------------------------------
__device__ __forceinline__ u64 pack2(float lo, float hi) {
    u64 r; asm("mov.b64 %0, {%1, %2};" : "=l"(r) : "f"(lo), "f"(hi)); return r;
}
__device__ __forceinline__ void unpack2(u64 v, float& lo, float& hi) {
    asm("mov.b64 {%0, %1}, %2;" : "=f"(lo), "=f"(hi) : "l"(v));
}
__device__ __forceinline__ u64 ffma2(u64 a, u64 b, u64 c) {
    u64 d; asm("fma.rn.f32x2 %0, %1, %2, %3;" : "=l"(d) : "l"(a), "l"(b), "l"(c)); return d;
}
__device__ __forceinline__ u64 fadd2(u64 a, u64 b) {
    u64 d; asm("add.rn.f32x2 %0, %1, %2;" : "=l"(d) : "l"(a), "l"(b)); return d;
}
__device__ __forceinline__ u64 fmul2(u64 a, u64 b) {
    u64 d; asm("mul.rn.f32x2 %0, %1, %2;" : "=l"(d) : "l"(a), "l"(b)); return d;
}
__device__ __forceinline__ float ex2(float x) {
    float r; asm("ex2.approx.f32 %0, %1;" : "=f"(r) : "f"(x)); return r;
}
// Input z' pre-scaled by log2e. True elu(z)+1 = ln2*max(z',0) + exp2(min(z',0)).
__device__ __forceinline__ float elup1s(float zp) {
    return fmaf(fmaxf(zp, 0.f), LN2, ex2(fminf(zp, 0.f)));
}
__device__ __forceinline__ u64 elup1s_2(u64 z) {
    float lo, hi; unpack2(z, lo, hi);
    return pack2(elup1s(lo), elup1s(hi));
}

// ---------------------------------------------------------------------------
// Kernel A: w_act[m,l] = sigmoid(r[l] - ||ml[m]-mu[l]||^2), smem-staged.
// ---------------------------------------------------------------------------
#define MT 32
#define DPAD 32

__global__ __launch_bounds__(256) void k_wact(const float* __restrict__ ml,
                                              const float* __restrict__ mu,
                                              const float* __restrict__ r) {
    __shared__ __align__(16) float s_mu[LL * DPAD];
    __shared__ __align__(16) float s_ml[MT * DPAD];
    __shared__ float s_r[LL];
    int tid = threadIdx.x;
    int m0  = blockIdx.x * MT;

    for (int e = tid; e < LL * DB; e += 256) {
        int l = e / DB, d = e % DB;
        s_mu[l * DPAD + d] = mu[e];
    }
    for (int e = tid; e < MT * DB; e += 256) {
        int mm = e / DB, d = e % DB;
        int m = m0 + mm;
        s_ml[mm * DPAD + d] = (m < NB) ? ml[m * DB + d] : 0.f;
    }
    if (tid < LL) s_r[tid] = r[tid];
    __syncthreads();

    int mm = tid & 31;
    int lg = tid >> 5;
    int m  = m0 + mm;
    if (m >= NB) return;

    float a[DB];
#pragma unroll
    for (int d = 0; d < DB; d++) a[d] = s_ml[mm * DPAD + d];

#pragma unroll
    for (int li = 0; li < 5; li++) {
        int l = lg * 5 + li;
        const float* c = &s_mu[l * DPAD];
        float s = 0.f;
#pragma unroll
        for (int d = 0; d < DB; d++) { float t = a[d] - c[d]; s = fmaf(t, t, s); }
        float z = s_r[l] - s;
        d_wact[m * LL + l] = 1.0f / (1.0f + __expf(-z));
    }
}

// ---------------------------------------------------------------------------
// Kernel B: gT[l,b] = sum_m x[b,m] * w_act[m,l]
// XS/WS = 132: 16B-aligned float4 rows, only 2-way bank conflicts.
// ---------------------------------------------------------------------------
#define CH 128
#define XS 132
#define WS 132

__global__ __launch_bounds__(320) void k_gemm(const float* __restrict__ x) {
    __shared__ __align__(16) float xs[16 * XS];
    __shared__ __align__(16) float ws[LL * WS];     // [l][mm]
    int b0  = blockIdx.x * 16;
    int tid = threadIdx.x;
    int row = tid & 15;
    int cg  = tid >> 4;
    u64 acc0 = 0ull, acc1 = 0ull;
    for (int m0 = 0; m0 < NB; m0 += CH) {
        for (int e = tid; e < 16 * CH; e += 320) {
            int rr = e >> 7, cc = e & (CH - 1);
            int m = m0 + cc;
            xs[rr * XS + cc] = (m < NB) ? x[(b0 + rr) * NB + m] : 0.f;
        }
        for (int e = tid; e < CH * LL; e += 320) {
            int mm = e / LL, l = e % LL;
            int m = m0 + mm;
            ws[l * WS + mm] = (m < NB) ? d_wact[m * LL + l] : 0.f;
        }
        __syncthreads();
#pragma unroll 4
        for (int mm = 0; mm < CH; mm += 4) {
            float4 xv = *(const float4*)&xs[row * XS + mm];
            float4 w0 = *(const float4*)&ws[(2 * cg)     * WS + mm];
            float4 w1 = *(const float4*)&ws[(2 * cg + 1) * WS + mm];
            u64 xa = pack2(xv.x, xv.y), xb = pack2(xv.z, xv.w);
            acc0 = ffma2(xa, pack2(w0.x, w0.y), acc0);
            acc0 = ffma2(xb, pack2(w0.z, w0.w), acc0);
            acc1 = ffma2(xa, pack2(w1.x, w1.y), acc1);
            acc1 = ffma2(xb, pack2(w1.z, w1.w), acc1);
        }
        __syncthreads();
    }
    float a0l, a0h, a1l, a1h;
    unpack2(acc0, a0l, a0h);
    unpack2(acc1, a1l, a1h);
    d_gT[(2 * cg)     * Bn + b0 + row] = a0l + a0h;
    d_gT[(2 * cg + 1) * Bn + b0 + row] = a1l + a1h;
}

// ---------------------------------------------------------------------------
// Kernel C: NAM. 128-thread blocks, 3 blocks/SM target. Each block = one
// (k,l) x one batch-half (1024 elems). Per thread: 2 passes x 2 pairs; each
// weight LDS.128 feeds 4 ffma2 (two pairs) -> low L1 traffic AND 12 warps/SM.
// Layers 1-3 pre-scaled by log2e; elu computed as elu+1 (bias-adjusted).
// ---------------------------------------------------------------------------
__global__ __launch_bounds__(128, 3) void k_nam(
    const float* __restrict__ W1, const float* __restrict__ b1,
    const float* __restrict__ W2, const float* __restrict__ b2,
    const float* __restrict__ W3, const float* __restrict__ b3,
    const float* __restrict__ W4, const float* __restrict__ b4,
    const float* __restrict__ alpha) {
    __shared__ __align__(16) ulonglong2 sL1[PP][16];   // (w_dup, b_dup) * log2e
    __shared__ __align__(16) u64 sB2d[PP][16];         // (b2 - rowsum W2)*log2e
    __shared__ __align__(16) u64 sW2d[PP][16][16];     // dup(W2[i][j])*log2e at [p][j][i]
    __shared__ __align__(16) u64 sW3d[PP][8][16];      // dup(W3[i][j])*log2e at [p][j][i]
    __shared__ __align__(16) u64 sB3d[PP][8], sW4d[PP][8];
    __shared__ __align__(16) u64 sB4d[PP];

    int bid  = blockIdx.x;
    int half = bid & 1;
    int kl   = bid >> 1;
    int k = kl / LL, l = kl % LL;
    int tid  = threadIdx.x;
    int base = (k * LL + l) * PP;

    if (tid < 32) {
        int p = tid >> 4, i = tid & 15;
        float w = W1[base * 16 + tid] * LOG2E;
        float a = b1[base * 16 + tid] * LOG2E;
        sL1[p][i] = make_ulonglong2(pack2(w, w), pack2(a, a));
        float c = b2[base * 16 + tid];
        const float* w2p = W2 + base * 256 + p * 256;
#pragma unroll
        for (int ii = 0; ii < 16; ii++) c -= w2p[ii * 16 + i];
        c *= LOG2E;
        sB2d[p][i] = pack2(c, c);
    }
#pragma unroll
    for (int e = tid; e < PP * 256; e += 128) {
        int p = e >> 8, i = (e >> 4) & 15, j = e & 15;
        float w = W2[base * 256 + e] * LOG2E;
        sW2d[p][j][i] = pack2(w, w);
    }
#pragma unroll
    for (int e = tid; e < PP * 128; e += 128) {
        int p = e >> 7, i = (e >> 3) & 15, j = e & 7;
        float w = W3[base * 128 + e] * LOG2E;
        sW3d[p][j][i] = pack2(w, w);
    }
    if (tid < 16) {
        int p = tid >> 3, j = tid & 7;
        float a = b3[base * 8 + tid];
        const float* w3p = W3 + base * 128 + p * 128;
#pragma unroll
        for (int ii = 0; ii < 16; ii++) a -= w3p[ii * 8 + j];
        a *= LOG2E;
        sB3d[p][j] = pack2(a, a);
        float w = W4[base * 8 + tid];  sW4d[p][j] = pack2(w, w);
    }
    if (tid < 2) {
        float a = b4[base + tid];
        const float* w4p = W4 + base * 8 + tid * 8;
#pragma unroll
        for (int ii = 0; ii < 8; ii++) a -= w4p[ii];
        sB4d[tid] = pack2(a, a);
    }
    __syncthreads();

    float aAct = 1.0f / (1.0f + __expf(-alpha[l * KK + k]));
    u64 aAct2 = pack2(aAct, aAct);
    float* outp = d_partial + (l * KK + k) * Bn + half * 1024;
    const float* gp = d_gT + l * Bn + half * 1024;

#pragma unroll 1
    for (int pass = 0; pass < 2; pass++) {
        int b0 = pass * 512 + 2 * tid;             // pair0 at b0, pair1 at b0+256
        float2 g0 = *(const float2*)&gp[b0];
        float2 g1 = *(const float2*)&gp[b0 + 256];
        u64 G0 = pack2(g0.x, g0.y);
        u64 G1 = pack2(g1.x, g1.y);
        u64 S0 = 0ull, S1 = 0ull;

#pragma unroll 1
        for (int p = 0; p < PP; p++) {
            u64 t1[16][2];
#pragma unroll
            for (int i = 0; i < 16; i++) {
                ulonglong2 wb = sL1[p][i];
                t1[i][0] = elup1s_2(ffma2(G0, wb.x, wb.y));
                t1[i][1] = elup1s_2(ffma2(G1, wb.x, wb.y));
            }

            u64 t2[16][2];
#pragma unroll
            for (int j = 0; j < 16; j++) {
                const ulonglong2* wr = (const ulonglong2*)sW2d[p][j];
                u64 bias = sB2d[p][j];
                u64 e0 = bias, o0 = 0ull, e1 = bias, o1 = 0ull;
#pragma unroll
                for (int q = 0; q < 8; q++) {
                    ulonglong2 w = wr[q];
                    e0 = ffma2(t1[2 * q][0],     w.x, e0);
                    o0 = ffma2(t1[2 * q + 1][0], w.y, o0);
                    e1 = ffma2(t1[2 * q][1],     w.x, e1);
                    o1 = ffma2(t1[2 * q + 1][1], w.y, o1);
                }
                t2[j][0] = elup1s_2(fadd2(e0, o0));
                t2[j][1] = elup1s_2(fadd2(e1, o1));
            }

            u64 t3[8][2];
#pragma unroll
            for (int j = 0; j < 8; j++) {
                const ulonglong2* wr = (const ulonglong2*)sW3d[p][j];
                u64 bias = sB3d[p][j];
                u64 e0 = bias, o0 = 0ull, e1 = bias, o1 = 0ull;
#pragma unroll
                for (int q = 0; q < 8; q++) {
                    ulonglong2 w = wr[q];
                    e0 = ffma2(t2[2 * q][0],     w.x, e0);
                    o0 = ffma2(t2[2 * q + 1][0], w.y, o0);
                    e1 = ffma2(t2[2 * q][1],     w.x, e1);
                    o1 = ffma2(t2[2 * q + 1][1], w.y, o1);
                }
                t3[j][0] = elup1s_2(fadd2(e0, o0));
                t3[j][1] = elup1s_2(fadd2(e1, o1));
            }

            {
                const ulonglong2* wr = (const ulonglong2*)sW4d[p];
                u64 bias = sB4d[p];
                u64 e0 = bias, o0 = 0ull, e1 = bias, o1 = 0ull;
#pragma unroll
                for (int q = 0; q < 4; q++) {
                    ulonglong2 w = wr[q];
                    e0 = ffma2(t3[2 * q][0],     w.x, e0);
                    o0 = ffma2(t3[2 * q + 1][0], w.y, o0);
                    e1 = ffma2(t3[2 * q][1],     w.x, e1);
                    o1 = ffma2(t3[2 * q + 1][1], w.y, o1);
                }
                S0 = fadd2(S0, fadd2(e0, o0));
                S1 = fadd2(S1, fadd2(e1, o1));
            }
        }

        u64 r0 = fmul2(aAct2, S0);
        u64 r1 = fmul2(aAct2, S1);
        float lo, hi;
        unpack2(r0, lo, hi); *(float2*)&outp[b0]       = make_float2(lo, hi);
        unpack2(r1, lo, hi); *(float2*)&outp[b0 + 256] = make_float2(lo, hi);
    }
}

// ---------------------------------------------------------------------------
// Kernel D: out[b,k] = beta[k] + sum_l partial[l,k,b]
// ---------------------------------------------------------------------------
__global__ void k_out(const float* __restrict__ beta, float* __restrict__ out) {
    int idx = blockIdx.x * blockDim.x + threadIdx.x;
    if (idx >= KK * Bn) return;
    int k = idx >> 11;
    int b = idx & (Bn - 1);
    float s = beta[k];
#pragma unroll
    for (int l = 0; l < LL; l++) s += d_partial[(l * KK + k) * Bn + b];
    out[b * KK + k] = s;
}

// ---------------------------------------------------------------------------
extern "C" void kernel_launch(void* const* d_in, const int* in_sizes, int n_in,
                              void* d_out, int out_size) {
    const float* x     = (const float*)d_in[0];
    const float* ml    = (const float*)d_in[1];
    const float* mu    = (const float*)d_in[2];
    const float* r     = (const float*)d_in[3];
    const float* alpha = (const float*)d_in[4];
    const float* beta  = (const float*)d_in[5];
    const float* W1    = (const float*)d_in[6];
    const float* b1    = (const float*)d_in[7];
    const float* W2    = (const float*)d_in[8];
    const float* b2    = (const float*)d_in[9];
    const float* W3    = (const float*)d_in[10];
    const float* b3    = (const float*)d_in[11];
    const float* W4    = (const float*)d_in[12];
    const float* b4    = (const float*)d_in[13];
    float* out = (float*)d_out;

    k_wact<<<(NB + MT - 1) / MT, 256>>>(ml, mu, r);
    k_gemm<<<Bn / 16, 320>>>(x);
    k_nam<<<KK * LL * 2, 128>>>(W1, b1, W2, b2, W3, b3, W4, b4, alpha);
    k_out<<<(KK * Bn + 255) / 256, 256>>>(beta, out);
}

// round 7
// speedup vs baseline: 1.4822x; 1.2520x over previous
#include <cuda_runtime.h>

#define Bn 2048
#define NB 2000
#define DB 30
#define KK 20
#define LL 40
#define PP 2
#define KSPLIT 4
#define KCH 500         // NB / KSPLIT

typedef unsigned long long u64;

#define LOG2E 1.44269504088896f
#define LN2   0.69314718055995f

// Scratch (no allocations allowed in kernel_launch)
__device__ float d_wact[NB * LL];               // sigmoid(r - kappa)   [NB, L]
__device__ float d_gpart[KSPLIT * LL * Bn];     // split-K partials     [ks, L, B]
__device__ float d_partial[LL * KK * Bn];       // per-(l,k) outputs    [L, K, B]

// ---------------- packed f32x2 helpers --------------------------------------
__device__ __forceinline__ u64 pack2(float lo, float hi) {
    u64 r; asm("mov.b64 %0, {%1, %2};" : "=l"(r) : "f"(lo), "f"(hi)); return r;
}
__device__ __forceinline__ void unpack2(u64 v, float& lo, float& hi) {
    asm("mov.b64 {%0, %1}, %2;" : "=f"(lo), "=f"(hi) : "l"(v));
}
__device__ __forceinline__ u64 ffma2(u64 a, u64 b, u64 c) {
    u64 d; asm("fma.rn.f32x2 %0, %1, %2, %3;" : "=l"(d) : "l"(a), "l"(b), "l"(c)); return d;
}
__device__ __forceinline__ u64 fadd2(u64 a, u64 b) {
    u64 d; asm("add.rn.f32x2 %0, %1, %2;" : "=l"(d) : "l"(a), "l"(b)); return d;
}
__device__ __forceinline__ u64 fmul2(u64 a, u64 b) {
    u64 d; asm("mul.rn.f32x2 %0, %1, %2;" : "=l"(d) : "l"(a), "l"(b)); return d;
}
__device__ __forceinline__ float ex2(float x) {
    float r; asm("ex2.approx.f32 %0, %1;" : "=f"(r) : "f"(x)); return r;
}
// Input z' pre-scaled by log2e. True elu(z)+1 = ln2*max(z',0) + exp2(min(z',0)).
__device__ __forceinline__ float elup1s(float zp) {
    return fmaf(fmaxf(zp, 0.f), LN2, ex2(fminf(zp, 0.f)));
}
__device__ __forceinline__ u64 elup1s_2(u64 z) {
    float lo, hi; unpack2(z, lo, hi);
    return pack2(elup1s(lo), elup1s(hi));
}

// ---------------------------------------------------------------------------
// Kernel A: w_act[m,l] = sigmoid(r[l] - ||ml[m]-mu[l]||^2), smem-staged.
// ---------------------------------------------------------------------------
#define MT 32
#define DPAD 32

__global__ __launch_bounds__(256) void k_wact(const float* __restrict__ ml,
                                              const float* __restrict__ mu,
                                              const float* __restrict__ r) {
    __shared__ __align__(16) float s_mu[LL * DPAD];
    __shared__ __align__(16) float s_ml[MT * DPAD];
    __shared__ float s_r[LL];
    int tid = threadIdx.x;
    int m0  = blockIdx.x * MT;

    for (int e = tid; e < LL * DB; e += 256) {
        int l = e / DB, d = e % DB;
        s_mu[l * DPAD + d] = mu[e];
    }
    for (int e = tid; e < MT * DB; e += 256) {
        int mm = e / DB, d = e % DB;
        int m = m0 + mm;
        s_ml[mm * DPAD + d] = (m < NB) ? ml[m * DB + d] : 0.f;
    }
    if (tid < LL) s_r[tid] = r[tid];
    __syncthreads();

    int mm = tid & 31;
    int lg = tid >> 5;
    int m  = m0 + mm;
    if (m >= NB) return;

    float a[DB];
#pragma unroll
    for (int d = 0; d < DB; d++) a[d] = s_ml[mm * DPAD + d];

#pragma unroll
    for (int li = 0; li < 5; li++) {
        int l = lg * 5 + li;
        const float* c = &s_mu[l * DPAD];
        float s = 0.f;
#pragma unroll
        for (int d = 0; d < DB; d++) { float t = a[d] - c[d]; s = fmaf(t, t, s); }
        float z = s_r[l] - s;
        d_wact[m * LL + l] = 1.0f / (1.0f + __expf(-z));
    }
}

// ---------------------------------------------------------------------------
// Kernel B: split-K GEMM. gpart[ks,l,b] = sum_{m in slice ks} x[b,m]*wact[m,l]
// grid (B/16, KSPLIT); 512 blocks -> ~3.5 blocks/SM, latency covered.
// ---------------------------------------------------------------------------
#define CH 128
#define XS 132
#define WS 132

__global__ __launch_bounds__(320) void k_gemm(const float* __restrict__ x) {
    __shared__ __align__(16) float xs[16 * XS];
    __shared__ __align__(16) float ws[LL * WS];     // [l][mm]
    int b0   = blockIdx.x * 16;
    int ks   = blockIdx.y;
    int mlo  = ks * KCH;
    int mend = mlo + KCH;
    int tid = threadIdx.x;
    int row = tid & 15;
    int cg  = tid >> 4;
    u64 acc0 = 0ull, acc1 = 0ull;
    for (int m0 = mlo; m0 < mend; m0 += CH) {
        for (int e = tid; e < 16 * CH; e += 320) {
            int rr = e >> 7, cc = e & (CH - 1);
            int m = m0 + cc;
            xs[rr * XS + cc] = (m < mend) ? x[(b0 + rr) * NB + m] : 0.f;
        }
        for (int e = tid; e < CH * LL; e += 320) {
            int mm = e / LL, l = e % LL;
            int m = m0 + mm;
            ws[l * WS + mm] = (m < mend) ? d_wact[m * LL + l] : 0.f;
        }
        __syncthreads();
#pragma unroll 4
        for (int mm = 0; mm < CH; mm += 4) {
            float4 xv = *(const float4*)&xs[row * XS + mm];
            float4 w0 = *(const float4*)&ws[(2 * cg)     * WS + mm];
            float4 w1 = *(const float4*)&ws[(2 * cg + 1) * WS + mm];
            u64 xa = pack2(xv.x, xv.y), xb = pack2(xv.z, xv.w);
            acc0 = ffma2(xa, pack2(w0.x, w0.y), acc0);
            acc0 = ffma2(xb, pack2(w0.z, w0.w), acc0);
            acc1 = ffma2(xa, pack2(w1.x, w1.y), acc1);
            acc1 = ffma2(xb, pack2(w1.z, w1.w), acc1);
        }
        __syncthreads();
    }
    float a0l, a0h, a1l, a1h;
    unpack2(acc0, a0l, a0h);
    unpack2(acc1, a1l, a1h);
    float* gp = d_gpart + ks * (LL * Bn);
    gp[(2 * cg)     * Bn + b0 + row] = a0l + a0h;
    gp[(2 * cg + 1) * Bn + b0 + row] = a1l + a1h;
}

// ---------------------------------------------------------------------------
// Kernel C: NAM. 128-thread blocks, 3 blocks/SM. Each block = one (k,l) x one
// batch-half. Per thread: 2 passes x 2 pairs; each weight LDS.128 feeds 4
// ffma2. g is reconstructed from the 4 split-K partials on load.
// ---------------------------------------------------------------------------
__global__ __launch_bounds__(128, 3) void k_nam(
    const float* __restrict__ W1, const float* __restrict__ b1,
    const float* __restrict__ W2, const float* __restrict__ b2,
    const float* __restrict__ W3, const float* __restrict__ b3,
    const float* __restrict__ W4, const float* __restrict__ b4,
    const float* __restrict__ alpha) {
    __shared__ __align__(16) ulonglong2 sL1[PP][16];   // (w_dup, b_dup) * log2e
    __shared__ __align__(16) u64 sB2d[PP][16];         // (b2 - rowsum W2)*log2e
    __shared__ __align__(16) u64 sW2d[PP][16][16];     // dup(W2[i][j])*log2e at [p][j][i]
    __shared__ __align__(16) u64 sW3d[PP][8][16];      // dup(W3[i][j])*log2e at [p][j][i]
    __shared__ __align__(16) u64 sB3d[PP][8], sW4d[PP][8];
    __shared__ __align__(16) u64 sB4d[PP];

    int bid  = blockIdx.x;
    int half = bid & 1;
    int kl   = bid >> 1;
    int k = kl / LL, l = kl % LL;
    int tid  = threadIdx.x;
    int base = (k * LL + l) * PP;

    if (tid < 32) {
        int p = tid >> 4, i = tid & 15;
        float w = W1[base * 16 + tid] * LOG2E;
        float a = b1[base * 16 + tid] * LOG2E;
        sL1[p][i] = make_ulonglong2(pack2(w, w), pack2(a, a));
        float c = b2[base * 16 + tid];
        const float* w2p = W2 + base * 256 + p * 256;
#pragma unroll
        for (int ii = 0; ii < 16; ii++) c -= w2p[ii * 16 + i];
        c *= LOG2E;
        sB2d[p][i] = pack2(c, c);
    }
#pragma unroll
    for (int e = tid; e < PP * 256; e += 128) {
        int p = e >> 8, i = (e >> 4) & 15, j = e & 15;
        float w = W2[base * 256 + e] * LOG2E;
        sW2d[p][j][i] = pack2(w, w);
    }
#pragma unroll
    for (int e = tid; e < PP * 128; e += 128) {
        int p = e >> 7, i = (e >> 3) & 15, j = e & 7;
        float w = W3[base * 128 + e] * LOG2E;
        sW3d[p][j][i] = pack2(w, w);
    }
    if (tid < 16) {
        int p = tid >> 3, j = tid & 7;
        float a = b3[base * 8 + tid];
        const float* w3p = W3 + base * 128 + p * 128;
#pragma unroll
        for (int ii = 0; ii < 16; ii++) a -= w3p[ii * 8 + j];
        a *= LOG2E;
        sB3d[p][j] = pack2(a, a);
        float w = W4[base * 8 + tid];  sW4d[p][j] = pack2(w, w);
    }
    if (tid < 2) {
        float a = b4[base + tid];
        const float* w4p = W4 + base * 8 + tid * 8;
#pragma unroll
        for (int ii = 0; ii < 8; ii++) a -= w4p[ii];
        sB4d[tid] = pack2(a, a);
    }
    __syncthreads();

    float aAct = 1.0f / (1.0f + __expf(-alpha[l * KK + k]));
    u64 aAct2 = pack2(aAct, aAct);
    float* outp = d_partial + (l * KK + k) * Bn + half * 1024;
    const float* gp = d_gpart + l * Bn + half * 1024;

#pragma unroll 1
    for (int pass = 0; pass < 2; pass++) {
        int b0 = pass * 512 + 2 * tid;             // pair0 at b0, pair1 at b0+256
        u64 G0, G1;
        {
            float2 a0 = *(const float2*)&gp[b0];
            float2 a1 = *(const float2*)&gp[LL * Bn + b0];
            float2 a2 = *(const float2*)&gp[2 * LL * Bn + b0];
            float2 a3 = *(const float2*)&gp[3 * LL * Bn + b0];
            G0 = fadd2(fadd2(pack2(a0.x, a0.y), pack2(a1.x, a1.y)),
                       fadd2(pack2(a2.x, a2.y), pack2(a3.x, a3.y)));
            float2 c0 = *(const float2*)&gp[b0 + 256];
            float2 c1 = *(const float2*)&gp[LL * Bn + b0 + 256];
            float2 c2 = *(const float2*)&gp[2 * LL * Bn + b0 + 256];
            float2 c3 = *(const float2*)&gp[3 * LL * Bn + b0 + 256];
            G1 = fadd2(fadd2(pack2(c0.x, c0.y), pack2(c1.x, c1.y)),
                       fadd2(pack2(c2.x, c2.y), pack2(c3.x, c3.y)));
        }
        u64 S0 = 0ull, S1 = 0ull;

#pragma unroll 1
        for (int p = 0; p < PP; p++) {
            u64 t1[16][2];
#pragma unroll
            for (int i = 0; i < 16; i++) {
                ulonglong2 wb = sL1[p][i];
                t1[i][0] = elup1s_2(ffma2(G0, wb.x, wb.y));
                t1[i][1] = elup1s_2(ffma2(G1, wb.x, wb.y));
            }

            u64 t2[16][2];
#pragma unroll
            for (int j = 0; j < 16; j++) {
                const ulonglong2* wr = (const ulonglong2*)sW2d[p][j];
                u64 bias = sB2d[p][j];
                u64 e0 = bias, o0 = 0ull, e1 = bias, o1 = 0ull;
#pragma unroll
                for (int q = 0; q < 8; q++) {
                    ulonglong2 w = wr[q];
                    e0 = ffma2(t1[2 * q][0],     w.x, e0);
                    o0 = ffma2(t1[2 * q + 1][0], w.y, o0);
                    e1 = ffma2(t1[2 * q][1],     w.x, e1);
                    o1 = ffma2(t1[2 * q + 1][1], w.y, o1);
                }
                t2[j][0] = elup1s_2(fadd2(e0, o0));
                t2[j][1] = elup1s_2(fadd2(e1, o1));
            }

            u64 t3[8][2];
#pragma unroll
            for (int j = 0; j < 8; j++) {
                const ulonglong2* wr = (const ulonglong2*)sW3d[p][j];
                u64 bias = sB3d[p][j];
                u64 e0 = bias, o0 = 0ull, e1 = bias, o1 = 0ull;
#pragma unroll
                for (int q = 0; q < 8; q++) {
                    ulonglong2 w = wr[q];
                    e0 = ffma2(t2[2 * q][0],     w.x, e0);
                    o0 = ffma2(t2[2 * q + 1][0], w.y, o0);
                    e1 = ffma2(t2[2 * q][1],     w.x, e1);
                    o1 = ffma2(t2[2 * q + 1][1], w.y, o1);
                }
                t3[j][0] = elup1s_2(fadd2(e0, o0));
                t3[j][1] = elup1s_2(fadd2(e1, o1));
            }

            {
                const ulonglong2* wr = (const ulonglong2*)sW4d[p];
                u64 bias = sB4d[p];
                u64 e0 = bias, o0 = 0ull, e1 = bias, o1 = 0ull;
#pragma unroll
                for (int q = 0; q < 4; q++) {
                    ulonglong2 w = wr[q];
                    e0 = ffma2(t3[2 * q][0],     w.x, e0);
                    o0 = ffma2(t3[2 * q + 1][0], w.y, o0);
                    e1 = ffma2(t3[2 * q][1],     w.x, e1);
                    o1 = ffma2(t3[2 * q + 1][1], w.y, o1);
                }
                S0 = fadd2(S0, fadd2(e0, o0));
                S1 = fadd2(S1, fadd2(e1, o1));
            }
        }

        u64 r0 = fmul2(aAct2, S0);
        u64 r1 = fmul2(aAct2, S1);
        float lo, hi;
        unpack2(r0, lo, hi); *(float2*)&outp[b0]       = make_float2(lo, hi);
        unpack2(r1, lo, hi); *(float2*)&outp[b0 + 256] = make_float2(lo, hi);
    }
}

// ---------------------------------------------------------------------------
// Kernel D: out[b,k] = beta[k] + sum_l partial[l,k,b]
// ---------------------------------------------------------------------------
__global__ void k_out(const float* __restrict__ beta, float* __restrict__ out) {
    int idx = blockIdx.x * blockDim.x + threadIdx.x;
    if (idx >= KK * Bn) return;
    int k = idx >> 11;
    int b = idx & (Bn - 1);
    float s = beta[k];
#pragma unroll
    for (int l = 0; l < LL; l++) s += d_partial[(l * KK + k) * Bn + b];
    out[b * KK + k] = s;
}

// ---------------------------------------------------------------------------
extern "C" void kernel_launch(void* const* d_in, const int* in_sizes, int n_in,
                              void* d_out, int out_size) {
    const float* x     = (const float*)d_in[0];
    const float* ml    = (const float*)d_in[1];
    const float* mu    = (const float*)d_in[2];
    const float* r     = (const float*)d_in[3];
    const float* alpha = (const float*)d_in[4];
    const float* beta  = (const float*)d_in[5];
    const float* W1    = (const float*)d_in[6];
    const float* b1    = (const float*)d_in[7];
    const float* W2    = (const float*)d_in[8];
    const float* b2    = (const float*)d_in[9];
    const float* W3    = (const float*)d_in[10];
    const float* b3    = (const float*)d_in[11];
    const float* W4    = (const float*)d_in[12];
    const float* b4    = (const float*)d_in[13];
    float* out = (float*)d_out;

    k_wact<<<(NB + MT - 1) / MT, 256>>>(ml, mu, r);
    dim3 ggrid(Bn / 16, KSPLIT);
    k_gemm<<<ggrid, 320>>>(x);
    k_nam<<<KK * LL * 2, 128>>>(W1, b1, W2, b2, W3, b3, W4, b4, alpha);
    k_out<<<(KK * Bn + 255) / 256, 256>>>(beta, out);
}

// round 8
// speedup vs baseline: 1.5494x; 1.0453x over previous
#include <cuda_runtime.h>

#define Bn 2048
#define NB 2000
#define DB 30
#define KK 20
#define LL 40
#define PP 2
#define KSPLIT 4
#define KCH 500         // NB / KSPLIT

typedef unsigned long long u64;

#define LOG2E 1.44269504088896f
#define LN2   0.69314718055995f

// Scratch (no allocations allowed in kernel_launch)
__device__ float d_wact[NB * LL];               // sigmoid(r - kappa)   [NB, L]
__device__ float d_gpart[KSPLIT * LL * Bn];     // split-K partials     [ks, L, B]
__device__ float d_partial[LL * KK * Bn];       // per-(l,k) outputs    [L, K, B]

// ---------------- packed f32x2 helpers --------------------------------------
__device__ __forceinline__ u64 pack2(float lo, float hi) {
    u64 r; asm("mov.b64 %0, {%1, %2};" : "=l"(r) : "f"(lo), "f"(hi)); return r;
}
__device__ __forceinline__ void unpack2(u64 v, float& lo, float& hi) {
    asm("mov.b64 {%0, %1}, %2;" : "=f"(lo), "=f"(hi) : "l"(v));
}
__device__ __forceinline__ u64 ffma2(u64 a, u64 b, u64 c) {
    u64 d; asm("fma.rn.f32x2 %0, %1, %2, %3;" : "=l"(d) : "l"(a), "l"(b), "l"(c)); return d;
}
__device__ __forceinline__ u64 fadd2(u64 a, u64 b) {
    u64 d; asm("add.rn.f32x2 %0, %1, %2;" : "=l"(d) : "l"(a), "l"(b)); return d;
}
__device__ __forceinline__ u64 fmul2(u64 a, u64 b) {
    u64 d; asm("mul.rn.f32x2 %0, %1, %2;" : "=l"(d) : "l"(a), "l"(b)); return d;
}
__device__ __forceinline__ float ex2(float x) {
    float r; asm("ex2.approx.f32 %0, %1;" : "=f"(r) : "f"(x)); return r;
}
// Input z' pre-scaled by log2e. True elu(z)+1 = ln2*max(z',0) + exp2(min(z',0)).
__device__ __forceinline__ float elup1s(float zp) {
    return fmaf(fmaxf(zp, 0.f), LN2, ex2(fminf(zp, 0.f)));
}
__device__ __forceinline__ u64 elup1s_2(u64 z) {
    float lo, hi; unpack2(z, lo, hi);
    return pack2(elup1s(lo), elup1s(hi));
}

// ---------------------------------------------------------------------------
// Kernel A: w_act[m,l] = sigmoid(r[l] - ||ml[m]-mu[l]||^2), smem-staged.
// ---------------------------------------------------------------------------
#define MT 32
#define DPAD 32

__global__ __launch_bounds__(256) void k_wact(const float* __restrict__ ml,
                                              const float* __restrict__ mu,
                                              const float* __restrict__ r) {
    __shared__ __align__(16) float s_mu[LL * DPAD];
    __shared__ __align__(16) float s_ml[MT * DPAD];
    __shared__ float s_r[LL];
    int tid = threadIdx.x;
    int m0  = blockIdx.x * MT;

    for (int e = tid; e < LL * DB; e += 256) {
        int l = e / DB, d = e % DB;
        s_mu[l * DPAD + d] = mu[e];
    }
    for (int e = tid; e < MT * DB; e += 256) {
        int mm = e / DB, d = e % DB;
        int m = m0 + mm;
        s_ml[mm * DPAD + d] = (m < NB) ? ml[m * DB + d] : 0.f;
    }
    if (tid < LL) s_r[tid] = r[tid];
    __syncthreads();

    int mm = tid & 31;
    int lg = tid >> 5;
    int m  = m0 + mm;
    if (m >= NB) return;

    float a[DB];
#pragma unroll
    for (int d = 0; d < DB; d++) a[d] = s_ml[mm * DPAD + d];

#pragma unroll
    for (int li = 0; li < 5; li++) {
        int l = lg * 5 + li;
        const float* c = &s_mu[l * DPAD];
        float s = 0.f;
#pragma unroll
        for (int d = 0; d < DB; d++) { float t = a[d] - c[d]; s = fmaf(t, t, s); }
        float z = s_r[l] - s;
        d_wact[m * LL + l] = 1.0f / (1.0f + __expf(-z));
    }
}

// ---------------------------------------------------------------------------
// Kernel B: split-K GEMM. gpart[ks,l,b] = sum_{m in slice ks} x[b,m]*wact[m,l]
// ---------------------------------------------------------------------------
#define CH 128
#define XS 132
#define WS 132

__global__ __launch_bounds__(320) void k_gemm(const float* __restrict__ x) {
    __shared__ __align__(16) float xs[16 * XS];
    __shared__ __align__(16) float ws[LL * WS];     // [l][mm]
    int b0   = blockIdx.x * 16;
    int ks   = blockIdx.y;
    int mlo  = ks * KCH;
    int mend = mlo + KCH;
    int tid = threadIdx.x;
    int row = tid & 15;
    int cg  = tid >> 4;
    u64 acc0 = 0ull, acc1 = 0ull;
    for (int m0 = mlo; m0 < mend; m0 += CH) {
        for (int e = tid; e < 16 * CH; e += 320) {
            int rr = e >> 7, cc = e & (CH - 1);
            int m = m0 + cc;
            xs[rr * XS + cc] = (m < mend) ? x[(b0 + rr) * NB + m] : 0.f;
        }
        for (int e = tid; e < CH * LL; e += 320) {
            int mm = e / LL, l = e % LL;
            int m = m0 + mm;
            ws[l * WS + mm] = (m < mend) ? d_wact[m * LL + l] : 0.f;
        }
        __syncthreads();
#pragma unroll 4
        for (int mm = 0; mm < CH; mm += 4) {
            float4 xv = *(const float4*)&xs[row * XS + mm];
            float4 w0 = *(const float4*)&ws[(2 * cg)     * WS + mm];
            float4 w1 = *(const float4*)&ws[(2 * cg + 1) * WS + mm];
            u64 xa = pack2(xv.x, xv.y), xb = pack2(xv.z, xv.w);
            acc0 = ffma2(xa, pack2(w0.x, w0.y), acc0);
            acc0 = ffma2(xb, pack2(w0.z, w0.w), acc0);
            acc1 = ffma2(xa, pack2(w1.x, w1.y), acc1);
            acc1 = ffma2(xb, pack2(w1.z, w1.w), acc1);
        }
        __syncthreads();
    }
    float a0l, a0h, a1l, a1h;
    unpack2(acc0, a0l, a0h);
    unpack2(acc1, a1l, a1h);
    float* gp = d_gpart + ks * (LL * Bn);
    gp[(2 * cg)     * Bn + b0 + row] = a0l + a0h;
    gp[(2 * cg + 1) * Bn + b0 + row] = a1l + a1h;
}

// ---------------------------------------------------------------------------
// Kernel C: NAM, accumulator-streaming form. Each h1_i is ELU'd and streamed
// into 16 running a2[j] accumulators (row-major W2 — no transposes); same for
// L2->L3. Peak register liveness ~96 -> 4 blocks/SM, and ELU MUFU work is
// interleaved with accumulation ffma2 (no MUFU bursts).
// ---------------------------------------------------------------------------
__global__ __launch_bounds__(128, 4) void k_nam(
    const float* __restrict__ W1, const float* __restrict__ b1,
    const float* __restrict__ W2, const float* __restrict__ b2,
    const float* __restrict__ W3, const float* __restrict__ b3,
    const float* __restrict__ W4, const float* __restrict__ b4,
    const float* __restrict__ alpha) {
    __shared__ __align__(16) ulonglong2 sL1[PP][16];   // (w1,b1)*log2e dup
    __shared__ __align__(16) u64 sW2r[PP][16][16];     // dup(W2[i][j]*log2e)  row-major
    __shared__ __align__(16) u64 sB2d[PP][16];         // (b2 - rowsum W2)*log2e dup
    __shared__ __align__(16) u64 sW3r[PP][16][8];      // dup(W3[j][q]*log2e)  row-major
    __shared__ __align__(16) u64 sB3d[PP][8];          // (b3 - rowsum W3)*log2e dup
    __shared__ __align__(16) u64 sW4d[PP][8];          // dup(W4) raw
    __shared__ __align__(16) u64 sB4d[PP];             // (b4 - sum W4) raw dup

    int bid  = blockIdx.x;
    int half = bid & 1;
    int kl   = bid >> 1;
    int k = kl / LL, l = kl % LL;
    int tid  = threadIdx.x;
    int base = (k * LL + l) * PP;

    if (tid < 32) {
        int p = tid >> 4, i = tid & 15;
        float w = W1[base * 16 + tid] * LOG2E;
        float a = b1[base * 16 + tid] * LOG2E;
        sL1[p][i] = make_ulonglong2(pack2(w, w), pack2(a, a));
        float c = b2[base * 16 + tid];
        const float* w2p = W2 + base * 256 + p * 256;
#pragma unroll
        for (int ii = 0; ii < 16; ii++) c -= w2p[ii * 16 + i];
        c *= LOG2E;
        sB2d[p][i] = pack2(c, c);
    }
#pragma unroll
    for (int e = tid; e < PP * 256; e += 128) {     // direct layout, no transpose
        float w = W2[base * 256 + e] * LOG2E;
        ((u64*)sW2r)[e] = pack2(w, w);
    }
#pragma unroll
    for (int e = tid; e < PP * 128; e += 128) {     // direct layout
        float w = W3[base * 128 + e] * LOG2E;
        ((u64*)sW3r)[e] = pack2(w, w);
    }
    if (tid < 16) {
        int p = tid >> 3, j = tid & 7;
        float a = b3[base * 8 + tid];
        const float* w3p = W3 + base * 128 + p * 128;
#pragma unroll
        for (int ii = 0; ii < 16; ii++) a -= w3p[ii * 8 + j];
        a *= LOG2E;
        sB3d[p][j] = pack2(a, a);
        float w = W4[base * 8 + tid];  sW4d[p][j] = pack2(w, w);
    }
    if (tid < 2) {
        float a = b4[base + tid];
        const float* w4p = W4 + base * 8 + tid * 8;
#pragma unroll
        for (int ii = 0; ii < 8; ii++) a -= w4p[ii];
        sB4d[tid] = pack2(a, a);
    }
    __syncthreads();

    float aAct = 1.0f / (1.0f + __expf(-alpha[l * KK + k]));
    u64 aAct2 = pack2(aAct, aAct);
    float* outp = d_partial + (l * KK + k) * Bn + half * 1024;
    const float* gp = d_gpart + l * Bn + half * 1024;

#pragma unroll 1
    for (int pass = 0; pass < 2; pass++) {
        int b0 = pass * 512 + 2 * tid;             // pairA at b0, pairB at b0+256
        u64 GA, GB;
        {
            float2 a0 = *(const float2*)&gp[b0];
            float2 a1 = *(const float2*)&gp[LL * Bn + b0];
            float2 a2v = *(const float2*)&gp[2 * LL * Bn + b0];
            float2 a3v = *(const float2*)&gp[3 * LL * Bn + b0];
            GA = fadd2(fadd2(pack2(a0.x, a0.y), pack2(a1.x, a1.y)),
                       fadd2(pack2(a2v.x, a2v.y), pack2(a3v.x, a3v.y)));
            float2 c0 = *(const float2*)&gp[b0 + 256];
            float2 c1 = *(const float2*)&gp[LL * Bn + b0 + 256];
            float2 c2 = *(const float2*)&gp[2 * LL * Bn + b0 + 256];
            float2 c3 = *(const float2*)&gp[3 * LL * Bn + b0 + 256];
            GB = fadd2(fadd2(pack2(c0.x, c0.y), pack2(c1.x, c1.y)),
                       fadd2(pack2(c2.x, c2.y), pack2(c3.x, c3.y)));
        }
        u64 SA = 0ull, SB = 0ull;

#pragma unroll 1
        for (int p = 0; p < PP; p++) {
            // ---- layer 1 streamed into layer-2 accumulators ----
            u64 a2[16][2];
#pragma unroll
            for (int j = 0; j < 16; j++) {
                u64 bb = sB2d[p][j];
                a2[j][0] = bb; a2[j][1] = bb;
            }
#pragma unroll
            for (int i = 0; i < 16; i++) {
                ulonglong2 wb = sL1[p][i];
                u64 hA = elup1s_2(ffma2(GA, wb.x, wb.y));
                u64 hB = elup1s_2(ffma2(GB, wb.x, wb.y));
                const ulonglong2* wr = (const ulonglong2*)sW2r[p][i];
#pragma unroll
                for (int q = 0; q < 8; q++) {
                    ulonglong2 w = wr[q];
                    a2[2 * q][0]     = ffma2(hA, w.x, a2[2 * q][0]);
                    a2[2 * q + 1][0] = ffma2(hA, w.y, a2[2 * q + 1][0]);
                    a2[2 * q][1]     = ffma2(hB, w.x, a2[2 * q][1]);
                    a2[2 * q + 1][1] = ffma2(hB, w.y, a2[2 * q + 1][1]);
                }
            }

            // ---- layer 2 -> layer 3 accumulators ----
            u64 a3[8][2];
#pragma unroll
            for (int q = 0; q < 8; q++) {
                u64 bb = sB3d[p][q];
                a3[q][0] = bb; a3[q][1] = bb;
            }
#pragma unroll
            for (int j = 0; j < 16; j++) {
                u64 vA = elup1s_2(a2[j][0]);
                u64 vB = elup1s_2(a2[j][1]);
                const ulonglong2* wr = (const ulonglong2*)sW3r[p][j];
#pragma unroll
                for (int q = 0; q < 4; q++) {
                    ulonglong2 w = wr[q];
                    a3[2 * q][0]     = ffma2(vA, w.x, a3[2 * q][0]);
                    a3[2 * q + 1][0] = ffma2(vA, w.y, a3[2 * q + 1][0]);
                    a3[2 * q][1]     = ffma2(vB, w.x, a3[2 * q][1]);
                    a3[2 * q + 1][1] = ffma2(vB, w.y, a3[2 * q + 1][1]);
                }
            }

            // ---- layer 3 -> scalar ----
            u64 fA = sB4d[p], fB = sB4d[p];
#pragma unroll
            for (int j = 0; j < 8; j++) {
                u64 vA = elup1s_2(a3[j][0]);
                u64 vB = elup1s_2(a3[j][1]);
                u64 w = sW4d[p][j];
                fA = ffma2(vA, w, fA);
                fB = ffma2(vB, w, fB);
            }
            SA = fadd2(SA, fA);
            SB = fadd2(SB, fB);
        }

        u64 r0 = fmul2(aAct2, SA);
        u64 r1 = fmul2(aAct2, SB);
        float lo, hi;
        unpack2(r0, lo, hi); *(float2*)&outp[b0]       = make_float2(lo, hi);
        unpack2(r1, lo, hi); *(float2*)&outp[b0 + 256] = make_float2(lo, hi);
    }
}

// ---------------------------------------------------------------------------
// Kernel D: out[b,k] = beta[k] + sum_l partial[l,k,b]; float4 over b.
// ---------------------------------------------------------------------------
__global__ __launch_bounds__(128) void k_out(const float* __restrict__ beta,
                                             float* __restrict__ out) {
    int idx = blockIdx.x * blockDim.x + threadIdx.x;
    if (idx >= KK * (Bn / 4)) return;
    int k  = idx / (Bn / 4);
    int b0 = (idx % (Bn / 4)) * 4;
    float bv = beta[k];
    float4 s = make_float4(bv, bv, bv, bv);
#pragma unroll
    for (int l = 0; l < LL; l++) {
        float4 v = *(const float4*)&d_partial[(l * KK + k) * Bn + b0];
        s.x += v.x; s.y += v.y; s.z += v.z; s.w += v.w;
    }
    out[(b0 + 0) * KK + k] = s.x;
    out[(b0 + 1) * KK + k] = s.y;
    out[(b0 + 2) * KK + k] = s.z;
    out[(b0 + 3) * KK + k] = s.w;
}

// ---------------------------------------------------------------------------
extern "C" void kernel_launch(void* const* d_in, const int* in_sizes, int n_in,
                              void* d_out, int out_size) {
    const float* x     = (const float*)d_in[0];
    const float* ml    = (const float*)d_in[1];
    const float* mu    = (const float*)d_in[2];
    const float* r     = (const float*)d_in[3];
    const float* alpha = (const float*)d_in[4];
    const float* beta  = (const float*)d_in[5];
    const float* W1    = (const float*)d_in[6];
    const float* b1    = (const float*)d_in[7];
    const float* W2    = (const float*)d_in[8];
    const float* b2    = (const float*)d_in[9];
    const float* W3    = (const float*)d_in[10];
    const float* b3    = (const float*)d_in[11];
    const float* W4    = (const float*)d_in[12];
    const float* b4    = (const float*)d_in[13];
    float* out = (float*)d_out;

    k_wact<<<(NB + MT - 1) / MT, 256>>>(ml, mu, r);
    dim3 ggrid(Bn / 16, KSPLIT);
    k_gemm<<<ggrid, 320>>>(x);
    k_nam<<<KK * LL * 2, 128>>>(W1, b1, W2, b2, W3, b3, W4, b4, alpha);
    k_out<<<(KK * (Bn / 4) + 127) / 128, 128>>>(beta, out);
}